// round 9
// baseline (speedup 1.0000x reference)
#include <cuda_runtime.h>
#include <cuda_fp16.h>
#include <stdint.h>
#include <math.h>

#define BB 4
#define NN 2048
#define DD 256
#define KK 16
#define PTS 4
#define MROWS 64
#define NT 512

// smem byte offsets
#define OFF_HHI 0                 // H plane fp16 [64][256], swizzled (32KB)
#define OFF_XHI 32768             // x_k fp16 plane (32KB)
#define OFF_XF  65536             // x_k fp32 [64][260] (66560B)
#define OFF_B0  132096            // B hi chunk (32KB)
#define OFF_B1  164864            // B lo chunk (32KB)
#define OFF_SDEL 197632
#define OFF_SIDX 198400
#define OFF_SWD1 198656
#define OFF_SBD1 201728
#define SMEM_TOTAL 202752

__device__ int g_knn[BB * NN * KK];
// [gemm 0..2][hi chunks 0..3, lo chunks 4..7][16384 half] pre-swizzled B images
__device__ __half g_wsplit[3 * 8 * 16384];

// ---------------------------------------------------------------------------
__device__ __forceinline__ uint32_t smem_u32(const void* p) {
    uint32_t a;
    asm("{ .reg .u64 t; cvta.to.shared.u64 t, %1; cvt.u32.u64 %0, t; }" : "=r"(a) : "l"(p));
    return a;
}
__device__ __forceinline__ void cp_async16(void* s, const void* g) {
    uint32_t a = smem_u32(s);
    asm volatile("cp.async.cg.shared.global [%0], [%1], 16;\n" :: "r"(a), "l"(g));
}
__device__ __forceinline__ void cp_commit() { asm volatile("cp.async.commit_group;\n"); }

__device__ __forceinline__ void ldsm4(uint32_t* r, uint32_t addr) {
    asm volatile("ldmatrix.sync.aligned.m8n8.x4.shared.b16 {%0,%1,%2,%3}, [%4];"
        : "=r"(r[0]), "=r"(r[1]), "=r"(r[2]), "=r"(r[3]) : "r"(addr));
}
__device__ __forceinline__ void mma16816(float* d, const uint32_t* a, uint32_t b0, uint32_t b1) {
    asm volatile("mma.sync.aligned.m16n8k16.row.col.f32.f16.f16.f32 "
        "{%0,%1,%2,%3}, {%4,%5,%6,%7}, {%8,%9}, {%0,%1,%2,%3};"
        : "+f"(d[0]), "+f"(d[1]), "+f"(d[2]), "+f"(d[3])
        : "r"(a[0]), "r"(a[1]), "r"(a[2]), "r"(a[3]), "r"(b0), "r"(b1));
}
__device__ __forceinline__ uint32_t pack2f(float v0, float v1) {
    __half2 h = __floats2half2_rn(v0, v1);
    return *(uint32_t*)&h;
}
// A-plane address: [64 rows][256 k] fp16, 512B rows, XOR swizzle in bits 4..6
__device__ __forceinline__ uint32_t aAddr(int row, int col) {
    return (uint32_t)row * 512 + (uint32_t)(((col * 2) ^ ((row & 7) << 4)));
}
// Stage one 32KB B term-chunk (256 n rows x 128B) linearly via cp.async
__device__ __forceinline__ void stage32(const __half* __restrict__ src, char* dst, int tid) {
    const float4* s = (const float4*)src;
#pragma unroll
    for (int i = 0; i < 4; i++)
        cp_async16(dst + (tid + i*NT)*16, s + tid + i*NT);
    cp_commit();
}

// ---------------------------------------------------------------------------
// prep: split fp32 weights into fp16 hi/lo, transpose to [n][k], pre-swizzle
// ---------------------------------------------------------------------------
__global__ void prep_kernel(const float* __restrict__ wd2, const float* __restrict__ wg1,
                            const float* __restrict__ wg2) {
    int t = blockIdx.x * 256 + threadIdx.x;
    if (t >= 3 * 65536) return;
    int g = t >> 16, k = (t >> 8) & 255, n = t & 255;
    const float* W = (g == 0) ? wd2 : ((g == 1) ? wg1 : wg2);
    float v = W[k * 256 + n];
    __half h = __float2half_rn(v);
    __half l = __float2half_rn(v - __half2float(h));
    int chunk = k >> 6, kb = k & 63;
    int byteoff = n * 128 + ((kb * 2) ^ ((n & 7) << 4));
    size_t base = (size_t)g * 8 * 16384;
    g_wsplit[base + (size_t)chunk * 16384 + (byteoff >> 1)] = h;
    g_wsplit[base + (size_t)(4 + chunk) * 16384 + (byteoff >> 1)] = l;
}

// ---------------------------------------------------------------------------
// KNN (validated)
// ---------------------------------------------------------------------------
__global__ __launch_bounds__(256) void knn_kernel(const float* __restrict__ xyz) {
    __shared__ float sx[NN], sy[NN], sz[NN], ssq[NN];
    int b  = blockIdx.x >> 8;
    int q0 = (blockIdx.x & 255) * 8;
    const float* base = xyz + (size_t)b * NN * 3;
    for (int i = threadIdx.x; i < NN; i += 256) {
        float x = base[i*3+0], y = base[i*3+1], z = base[i*3+2];
        sx[i] = x; sy[i] = y; sz[i] = z; ssq[i] = x*x + y*y + z*z;
    }
    __syncthreads();
    int lane = threadIdx.x & 31;
    int q = q0 + (threadIdx.x >> 5);
    float qx = sx[q], qy = sy[q], qz = sz[q], qsq = ssq[q];
    float bd[KK]; int bi[KK];
#pragma unroll
    for (int i = 0; i < KK; i++) { bd[i] = INFINITY; bi[i] = 0; }
    for (int m = lane; m < NN; m += 32) {
        float d = qsq - 2.0f*(qx*sx[m] + qy*sy[m] + qz*sz[m]) + ssq[m];
        if (d < bd[KK-1]) {
            float v = d; int vi = m;
#pragma unroll
            for (int j = 0; j < KK; j++)
                if (v < bd[j]) { float td = bd[j]; int ti = bi[j]; bd[j]=v; bi[j]=vi; v=td; vi=ti; }
        }
    }
    int sel = 0;
    for (int r = 0; r < KK; r++) {
        float m0 = bd[0]; int ml = lane;
#pragma unroll
        for (int off = 16; off; off >>= 1) {
            float om = __shfl_xor_sync(0xffffffffu, m0, off);
            int   ol = __shfl_xor_sync(0xffffffffu, ml, off);
            if (om < m0 || (om == m0 && ol < ml)) { m0 = om; ml = ol; }
        }
        int widx = __shfl_sync(0xffffffffu, bi[0], ml);
        if (lane == r) sel = widx;
        if (lane == ml) {
#pragma unroll
            for (int j = 0; j < KK-1; j++) { bd[j]=bd[j+1]; bi[j]=bi[j+1]; }
            bd[KK-1] = INFINITY;
        }
    }
    if (lane < KK) g_knn[((size_t)b*NN + q)*KK + lane] = sel;
}

// ---------------------------------------------------------------------------
// Emulated GEMM (2-pass): acc(64x256) += A @ (W_hi + W_lo)^T, A single fp16.
// Caller must have pre-staged chunk 0 (hi->B0, lo->B1, two commit groups).
// ---------------------------------------------------------------------------
__device__ __forceinline__ void run_gemm(const __half* __restrict__ wsplit_g,
                                         char* smemc, uint32_t sb, uint32_t aOff,
                                         float acc[8][4], int tid, int wm, int wn)
{
    int lane = tid & 31;
    int ar = lane & 15, ah = lane >> 4;
    uint32_t aRow = sb + (uint32_t)(16*wm + ar) * 512 + aOff;
    uint32_t aXor = (uint32_t)(ar & 7) << 4;
    int bi = lane & 7, bseg = lane >> 3;
    int bn_add = bi + ((bseg >= 2) ? 8 : 0);
    int bk_add = (bseg & 1) ? 8 : 0;
    uint32_t bXor = (uint32_t)bi << 4;
    uint32_t bRow = (uint32_t)(64*wn + bn_add) * 128;

#pragma unroll
    for (int t = 0; t < 8; t++)
#pragma unroll
        for (int j = 0; j < 4; j++) acc[t][j] = 0.f;

#pragma unroll 1
    for (int c = 0; c < 4; c++) {
        asm volatile("cp.async.wait_group 0;" ::: "memory");
        __syncthreads();
#pragma unroll
        for (int kstep = 0; kstep < 4; kstep++) {
            uint32_t aCol = (uint32_t)((c*64 + kstep*16 + 8*ah) * 2) ^ aXor;
            uint32_t aa[4];
            ldsm4(aa, aRow + aCol);
            uint32_t bOff = (uint32_t)((kstep*16 + bk_add) * 2) ^ bXor;
#pragma unroll
            for (int tp = 0; tp < 4; tp++) {
                uint32_t bh[4];
                ldsm4(bh, sb + OFF_B0 + bRow + (uint32_t)tp*2048 + bOff);
                mma16816(acc[2*tp],   aa, bh[0], bh[1]);
                mma16816(acc[2*tp+1], aa, bh[2], bh[3]);
            }
#pragma unroll
            for (int tp = 0; tp < 4; tp++) {
                uint32_t bl[4];
                ldsm4(bl, sb + OFF_B1 + bRow + (uint32_t)tp*2048 + bOff);
                mma16816(acc[2*tp],   aa, bl[0], bl[1]);
                mma16816(acc[2*tp+1], aa, bl[2], bl[3]);
            }
        }
        __syncthreads();
        if (c < 3) {
            stage32(wsplit_g + (size_t)(c + 1) * 16384, smemc + OFF_B0, tid);
            stage32(wsplit_g + (size_t)(5 + c) * 16384, smemc + OFF_B1, tid);
        }
    }
}

// ---------------------------------------------------------------------------
// Fused block: delta-MLP + gather + gating-MLP + softmax + residual. M=64.
// ---------------------------------------------------------------------------
__global__ __launch_bounds__(NT, 1)
void mlp_kernel(const float* __restrict__ xyz, const float* __restrict__ feat,
                const float* __restrict__ wd1, const float* __restrict__ bd1,
                const float* __restrict__ bd2, const float* __restrict__ bg1,
                const float* __restrict__ bg2, float* __restrict__ out)
{
    extern __shared__ char smemc[];
    uint32_t sb = smem_u32(smemc);
    int tid = threadIdx.x;
    int w = tid >> 5, lane = tid & 31;
    int wm = w & 3, wn = w >> 2;
    int b  = blockIdx.x >> 9;             // 512 CTAs per batch
    int p0 = (blockIdx.x & 511) * PTS;

    float* sdel = (float*)(smemc + OFF_SDEL);
    int*   sidx = (int*)(smemc + OFF_SIDX);
    float* swd1 = (float*)(smemc + OFF_SWD1);
    float* sbd1 = (float*)(smemc + OFF_SBD1);
    float* xf   = (float*)(smemc + OFF_XF);

    // pre-stage GEMM1 chunk 0 (hi + lo) as early as possible
    stage32(g_wsplit,            smemc + OFF_B0, tid);
    stage32(g_wsplit + 4*16384,  smemc + OFF_B1, tid);

    if (tid < 256) sbd1[tid] = bd1[tid];
    for (int i = tid; i < 768; i += NT) swd1[i] = wd1[i];
    if (tid < MROWS) {
        int n = p0 + (tid >> 4);
        int idx = g_knn[((size_t)b*NN + n)*KK + (tid & 15)];
        sidx[tid] = idx;
        const float* xb = xyz + (size_t)b * NN * 3;
        sdel[tid*3+0] = xb[n*3+0] - xb[idx*3+0];
        sdel[tid*3+1] = xb[n*3+1] - xb[idx*3+1];
        sdel[tid*3+2] = xb[n*3+2] - xb[idx*3+2];
    }
    __syncthreads();

    // ---- H1 = relu(delta @ wd1 + bd1) -> HHI (fp16) ----
    {
        int row = tid >> 3;
        int c0 = (tid & 7) * 32;
        float dx = sdel[row*3], dy = sdel[row*3+1], dz = sdel[row*3+2];
#pragma unroll
        for (int jp = 0; jp < 16; jp++) {
            int ch = c0 + jp*2;
            float v0 = fmaxf(fmaf(dz, swd1[512+ch],   fmaf(dy, swd1[256+ch],   fmaf(dx, swd1[ch],   sbd1[ch]))), 0.f);
            float v1 = fmaxf(fmaf(dz, swd1[512+ch+1], fmaf(dy, swd1[256+ch+1], fmaf(dx, swd1[ch+1], sbd1[ch+1]))), 0.f);
            *(uint32_t*)(smemc + OFF_HHI + aAddr(row, ch)) = pack2f(v0, v1);
        }
    }
    // (visibility covered by first wait+sync inside run_gemm)

    float acc[8][4];
    int ra = 16*wm + (lane >> 2), rb = ra + 8;

    // ---- GEMM1: D = H1 @ wd2^T ----
    run_gemm(g_wsplit, smemc, sb, OFF_HHI, acc, tid, wm, wn);

    // pre-stage GEMM2 chunk 0 (B buffers idle now, overlaps epi1)
    stage32(g_wsplit +  8*16384, smemc + OFF_B0, tid);
    stage32(g_wsplit + 12*16384, smemc + OFF_B1, tid);

    // ---- epi1: x_k = D + bd2 + feat[idx] -> XHI (fp16) + XF (fp32) ----
    {
        const float* fb = feat + (size_t)b * NN * DD;
        const float* fra = fb + (size_t)sidx[ra] * DD;
        const float* frb = fb + (size_t)sidx[rb] * DD;
#pragma unroll
        for (int t = 0; t < 8; t++) {
            int ne = 64*wn + 8*t + 2*(lane & 3);
            float2 fa = *(const float2*)(fra + ne);
            float2 fv = *(const float2*)(frb + ne);
            float bj0 = __ldg(&bd2[ne]), bj1 = __ldg(&bd2[ne+1]);
            float v0 = acc[t][0] + bj0 + fa.x;
            float v1 = acc[t][1] + bj1 + fa.y;
            float v2 = acc[t][2] + bj0 + fv.x;
            float v3 = acc[t][3] + bj1 + fv.y;
            *(uint32_t*)(smemc + OFF_XHI + aAddr(ra, ne)) = pack2f(v0, v1);
            *(uint32_t*)(smemc + OFF_XHI + aAddr(rb, ne)) = pack2f(v2, v3);
            *(float2*)(xf + ra*260 + ne) = make_float2(v0, v1);
            *(float2*)(xf + rb*260 + ne) = make_float2(v2, v3);
        }
    }

    // ---- GEMM2: D = x_k @ wg1^T ----
    run_gemm(g_wsplit + 8*16384, smemc, sb, OFF_XHI, acc, tid, wm, wn);

    // pre-stage GEMM3 chunk 0
    stage32(g_wsplit + 16*16384, smemc + OFF_B0, tid);
    stage32(g_wsplit + 20*16384, smemc + OFF_B1, tid);

    // ---- epi2: H2 = relu(D + bg1) -> HHI ----
    {
#pragma unroll
        for (int t = 0; t < 8; t++) {
            int ne = 64*wn + 8*t + 2*(lane & 3);
            float bj0 = __ldg(&bg1[ne]), bj1 = __ldg(&bg1[ne+1]);
            float v0 = fmaxf(acc[t][0] + bj0, 0.f);
            float v1 = fmaxf(acc[t][1] + bj1, 0.f);
            float v2 = fmaxf(acc[t][2] + bj0, 0.f);
            float v3 = fmaxf(acc[t][3] + bj1, 0.f);
            *(uint32_t*)(smemc + OFF_HHI + aAddr(ra, ne)) = pack2f(v0, v1);
            *(uint32_t*)(smemc + OFF_HHI + aAddr(rb, ne)) = pack2f(v2, v3);
        }
    }

    // ---- GEMM3: D = H2 @ wg2^T ----
    run_gemm(g_wsplit + 16*16384, smemc, sb, OFF_HHI, acc, tid, wm, wn);

    // ---- softmax over k (warp wm owns point wm's 16 rows) + weighted sum ----
    {
        int n_pt = p0 + wm;
        const float* fpt = feat + ((size_t)b*NN + n_pt) * DD;
        float* orow = out + ((size_t)b*NN + n_pt) * DD;
#pragma unroll
        for (int t = 0; t < 8; t++) {
            int ne = 64*wn + 8*t + 2*(lane & 3);
            float bj0 = __ldg(&bg2[ne]), bj1 = __ldg(&bg2[ne+1]);
            float g0 = acc[t][0] + bj0;
            float g1 = acc[t][1] + bj1;
            float g2 = acc[t][2] + bj0;
            float g3 = acc[t][3] + bj1;
            float2 xa = *(const float2*)(xf + ra*260 + ne);
            float2 xv = *(const float2*)(xf + rb*260 + ne);
            float m0 = fmaxf(g0, g2), m1 = fmaxf(g1, g3);
#pragma unroll
            for (int o = 4; o <= 16; o <<= 1) {
                m0 = fmaxf(m0, __shfl_xor_sync(0xffffffffu, m0, o));
                m1 = fmaxf(m1, __shfl_xor_sync(0xffffffffu, m1, o));
            }
            float e0 = __expf(g0 - m0), e2 = __expf(g2 - m0);
            float e1 = __expf(g1 - m1), e3 = __expf(g3 - m1);
            float se0 = e0 + e2, se1 = e1 + e3;
            float sx0 = e0*xa.x + e2*xv.x, sx1 = e1*xa.y + e3*xv.y;
#pragma unroll
            for (int o = 4; o <= 16; o <<= 1) {
                se0 += __shfl_xor_sync(0xffffffffu, se0, o);
                se1 += __shfl_xor_sync(0xffffffffu, se1, o);
                sx0 += __shfl_xor_sync(0xffffffffu, sx0, o);
                sx1 += __shfl_xor_sync(0xffffffffu, sx1, o);
            }
            if (lane < 4) {
                float2 f = *(const float2*)(fpt + ne);
                float2 o2 = make_float2(f.x + sx0/se0, f.y + sx1/se1);
                *(float2*)(orow + ne) = o2;
            }
        }
    }
}

// ---------------------------------------------------------------------------
extern "C" void kernel_launch(void* const* d_in, const int* in_sizes, int n_in,
                              void* d_out, int out_size) {
    const float* xyz  = (const float*)d_in[0];
    const float* feat = (const float*)d_in[1];
    const float* wd1  = (const float*)d_in[2];
    const float* bd1  = (const float*)d_in[3];
    const float* wd2  = (const float*)d_in[4];
    const float* bd2  = (const float*)d_in[5];
    const float* wg1  = (const float*)d_in[6];
    const float* bg1  = (const float*)d_in[7];
    const float* wg2  = (const float*)d_in[8];
    const float* bg2  = (const float*)d_in[9];
    float* out = (float*)d_out;

    prep_kernel<<<768, 256>>>(wd2, wg1, wg2);
    knn_kernel<<<BB * NN / 8, 256>>>(xyz);

    cudaFuncSetAttribute(mlp_kernel, cudaFuncAttributeMaxDynamicSharedMemorySize, SMEM_TOTAL);
    mlp_kernel<<<BB * NN / PTS, NT, SMEM_TOTAL>>>(xyz, feat, wd1, bd1,
                                                  bd2, bg1, bg2, out);
}

// round 10
// speedup vs baseline: 1.0006x; 1.0006x over previous
#include <cuda_runtime.h>
#include <cuda_fp16.h>
#include <stdint.h>
#include <math.h>

#define BB 4
#define NN 2048
#define DD 256
#define KK 16
#define PTS 4
#define MROWS 64
#define NT 512

// smem byte offsets
#define OFF_HHI 0                 // H plane fp16 [64][256], swizzled (32KB)
#define OFF_XHI 32768             // x_k fp16 plane (32KB)
#define OFF_XF  65536             // x_k fp32 [64][260] (66560B)
#define OFF_B0  132096            // B hi chunk (32KB)
#define OFF_B1  164864            // B lo chunk (32KB)
#define OFF_SDEL 197632
#define OFF_SIDX 198400
#define OFF_SWD1 198656
#define OFF_SBD1 201728
#define SMEM_TOTAL 202752

__device__ int g_knn[BB * NN * KK];
// [gemm 0..2][hi chunks 0..3, lo chunks 4..7][16384 half] pre-swizzled B images
__device__ __half g_wsplit[3 * 8 * 16384];

// ---------------------------------------------------------------------------
__device__ __forceinline__ uint32_t smem_u32(const void* p) {
    uint32_t a;
    asm("{ .reg .u64 t; cvta.to.shared.u64 t, %1; cvt.u32.u64 %0, t; }" : "=r"(a) : "l"(p));
    return a;
}
__device__ __forceinline__ void cp_async16(void* s, const void* g) {
    uint32_t a = smem_u32(s);
    asm volatile("cp.async.cg.shared.global [%0], [%1], 16;\n" :: "r"(a), "l"(g));
}
__device__ __forceinline__ void cp_commit() { asm volatile("cp.async.commit_group;\n"); }

__device__ __forceinline__ void ldsm4(uint32_t* r, uint32_t addr) {
    asm volatile("ldmatrix.sync.aligned.m8n8.x4.shared.b16 {%0,%1,%2,%3}, [%4];"
        : "=r"(r[0]), "=r"(r[1]), "=r"(r[2]), "=r"(r[3]) : "r"(addr));
}
__device__ __forceinline__ void mma16816(float* d, const uint32_t* a, uint32_t b0, uint32_t b1) {
    asm volatile("mma.sync.aligned.m16n8k16.row.col.f32.f16.f16.f32 "
        "{%0,%1,%2,%3}, {%4,%5,%6,%7}, {%8,%9}, {%0,%1,%2,%3};"
        : "+f"(d[0]), "+f"(d[1]), "+f"(d[2]), "+f"(d[3])
        : "r"(a[0]), "r"(a[1]), "r"(a[2]), "r"(a[3]), "r"(b0), "r"(b1));
}
__device__ __forceinline__ uint32_t pack2f(float v0, float v1) {
    __half2 h = __floats2half2_rn(v0, v1);
    return *(uint32_t*)&h;
}
// A-plane address: [64 rows][256 k] fp16, 512B rows, XOR swizzle in bits 4..6
__device__ __forceinline__ uint32_t aAddr(int row, int col) {
    return (uint32_t)row * 512 + (uint32_t)(((col * 2) ^ ((row & 7) << 4)));
}
// Stage one 32KB B term-chunk (256 n rows x 128B) linearly via cp.async
__device__ __forceinline__ void stage32(const __half* __restrict__ src, char* dst, int tid) {
    const float4* s = (const float4*)src;
#pragma unroll
    for (int i = 0; i < 4; i++)
        cp_async16(dst + (tid + i*NT)*16, s + tid + i*NT);
    cp_commit();
}

// ---------------------------------------------------------------------------
// prep: split fp32 weights into fp16 hi/lo, transpose to [n][k], pre-swizzle
// ---------------------------------------------------------------------------
__global__ void prep_kernel(const float* __restrict__ wd2, const float* __restrict__ wg1,
                            const float* __restrict__ wg2) {
    int t = blockIdx.x * 256 + threadIdx.x;
    if (t >= 3 * 65536) return;
    int g = t >> 16, k = (t >> 8) & 255, n = t & 255;
    const float* W = (g == 0) ? wd2 : ((g == 1) ? wg1 : wg2);
    float v = W[k * 256 + n];
    __half h = __float2half_rn(v);
    __half l = __float2half_rn(v - __half2float(h));
    int chunk = k >> 6, kb = k & 63;
    int byteoff = n * 128 + ((kb * 2) ^ ((n & 7) << 4));
    size_t base = (size_t)g * 8 * 16384;
    g_wsplit[base + (size_t)chunk * 16384 + (byteoff >> 1)] = h;
    g_wsplit[base + (size_t)(4 + chunk) * 16384 + (byteoff >> 1)] = l;
}

// ---------------------------------------------------------------------------
// KNN (validated)
// ---------------------------------------------------------------------------
__global__ __launch_bounds__(256) void knn_kernel(const float* __restrict__ xyz) {
    __shared__ float sx[NN], sy[NN], sz[NN], ssq[NN];
    int b  = blockIdx.x >> 8;
    int q0 = (blockIdx.x & 255) * 8;
    const float* base = xyz + (size_t)b * NN * 3;
    for (int i = threadIdx.x; i < NN; i += 256) {
        float x = base[i*3+0], y = base[i*3+1], z = base[i*3+2];
        sx[i] = x; sy[i] = y; sz[i] = z; ssq[i] = x*x + y*y + z*z;
    }
    __syncthreads();
    int lane = threadIdx.x & 31;
    int q = q0 + (threadIdx.x >> 5);
    float qx = sx[q], qy = sy[q], qz = sz[q], qsq = ssq[q];
    float bd[KK]; int bi[KK];
#pragma unroll
    for (int i = 0; i < KK; i++) { bd[i] = INFINITY; bi[i] = 0; }
    for (int m = lane; m < NN; m += 32) {
        float d = qsq - 2.0f*(qx*sx[m] + qy*sy[m] + qz*sz[m]) + ssq[m];
        if (d < bd[KK-1]) {
            float v = d; int vi = m;
#pragma unroll
            for (int j = 0; j < KK; j++)
                if (v < bd[j]) { float td = bd[j]; int ti = bi[j]; bd[j]=v; bi[j]=vi; v=td; vi=ti; }
        }
    }
    int sel = 0;
    for (int r = 0; r < KK; r++) {
        float m0 = bd[0]; int ml = lane;
#pragma unroll
        for (int off = 16; off; off >>= 1) {
            float om = __shfl_xor_sync(0xffffffffu, m0, off);
            int   ol = __shfl_xor_sync(0xffffffffu, ml, off);
            if (om < m0 || (om == m0 && ol < ml)) { m0 = om; ml = ol; }
        }
        int widx = __shfl_sync(0xffffffffu, bi[0], ml);
        if (lane == r) sel = widx;
        if (lane == ml) {
#pragma unroll
            for (int j = 0; j < KK-1; j++) { bd[j]=bd[j+1]; bi[j]=bi[j+1]; }
            bd[KK-1] = INFINITY;
        }
    }
    if (lane < KK) g_knn[((size_t)b*NN + q)*KK + lane] = sel;
}

// ---------------------------------------------------------------------------
// Emulated GEMM (2-pass): acc(64x256) += A @ (W_hi + W_lo)^T, A single fp16.
// Caller must have pre-staged chunk 0 (hi->B0, lo->B1, two commit groups).
// ---------------------------------------------------------------------------
__device__ __forceinline__ void run_gemm(const __half* __restrict__ wsplit_g,
                                         char* smemc, uint32_t sb, uint32_t aOff,
                                         float acc[8][4], int tid, int wm, int wn)
{
    int lane = tid & 31;
    int ar = lane & 15, ah = lane >> 4;
    uint32_t aRow = sb + (uint32_t)(16*wm + ar) * 512 + aOff;
    uint32_t aXor = (uint32_t)(ar & 7) << 4;
    int bi = lane & 7, bseg = lane >> 3;
    int bn_add = bi + ((bseg >= 2) ? 8 : 0);
    int bk_add = (bseg & 1) ? 8 : 0;
    uint32_t bXor = (uint32_t)bi << 4;
    uint32_t bRow = (uint32_t)(64*wn + bn_add) * 128;

#pragma unroll
    for (int t = 0; t < 8; t++)
#pragma unroll
        for (int j = 0; j < 4; j++) acc[t][j] = 0.f;

#pragma unroll 1
    for (int c = 0; c < 4; c++) {
        asm volatile("cp.async.wait_group 0;" ::: "memory");
        __syncthreads();
#pragma unroll
        for (int kstep = 0; kstep < 4; kstep++) {
            uint32_t aCol = (uint32_t)((c*64 + kstep*16 + 8*ah) * 2) ^ aXor;
            uint32_t aa[4];
            ldsm4(aa, aRow + aCol);
            uint32_t bOff = (uint32_t)((kstep*16 + bk_add) * 2) ^ bXor;
#pragma unroll
            for (int tp = 0; tp < 4; tp++) {
                uint32_t bh[4];
                ldsm4(bh, sb + OFF_B0 + bRow + (uint32_t)tp*2048 + bOff);
                mma16816(acc[2*tp],   aa, bh[0], bh[1]);
                mma16816(acc[2*tp+1], aa, bh[2], bh[3]);
            }
#pragma unroll
            for (int tp = 0; tp < 4; tp++) {
                uint32_t bl[4];
                ldsm4(bl, sb + OFF_B1 + bRow + (uint32_t)tp*2048 + bOff);
                mma16816(acc[2*tp],   aa, bl[0], bl[1]);
                mma16816(acc[2*tp+1], aa, bl[2], bl[3]);
            }
        }
        __syncthreads();
        if (c < 3) {
            stage32(wsplit_g + (size_t)(c + 1) * 16384, smemc + OFF_B0, tid);
            stage32(wsplit_g + (size_t)(5 + c) * 16384, smemc + OFF_B1, tid);
        }
    }
}

// ---------------------------------------------------------------------------
// Fused block: delta-MLP + gather + gating-MLP + softmax + residual. M=64.
// ---------------------------------------------------------------------------
__global__ __launch_bounds__(NT, 1)
void mlp_kernel(const float* __restrict__ xyz, const float* __restrict__ feat,
                const float* __restrict__ wd1, const float* __restrict__ bd1,
                const float* __restrict__ bd2, const float* __restrict__ bg1,
                const float* __restrict__ bg2, float* __restrict__ out)
{
    extern __shared__ char smemc[];
    uint32_t sb = smem_u32(smemc);
    int tid = threadIdx.x;
    int w = tid >> 5, lane = tid & 31;
    int wm = w & 3, wn = w >> 2;
    int b  = blockIdx.x >> 9;             // 512 CTAs per batch
    int p0 = (blockIdx.x & 511) * PTS;

    float* sdel = (float*)(smemc + OFF_SDEL);
    int*   sidx = (int*)(smemc + OFF_SIDX);
    float* swd1 = (float*)(smemc + OFF_SWD1);
    float* sbd1 = (float*)(smemc + OFF_SBD1);
    float* xf   = (float*)(smemc + OFF_XF);

    // pre-stage GEMM1 chunk 0 (hi + lo) as early as possible
    stage32(g_wsplit,            smemc + OFF_B0, tid);
    stage32(g_wsplit + 4*16384,  smemc + OFF_B1, tid);

    if (tid < 256) sbd1[tid] = bd1[tid];
    for (int i = tid; i < 768; i += NT) swd1[i] = wd1[i];
    if (tid < MROWS) {
        int n = p0 + (tid >> 4);
        int idx = g_knn[((size_t)b*NN + n)*KK + (tid & 15)];
        sidx[tid] = idx;
        const float* xb = xyz + (size_t)b * NN * 3;
        sdel[tid*3+0] = xb[n*3+0] - xb[idx*3+0];
        sdel[tid*3+1] = xb[n*3+1] - xb[idx*3+1];
        sdel[tid*3+2] = xb[n*3+2] - xb[idx*3+2];
    }
    __syncthreads();

    // ---- H1 = relu(delta @ wd1 + bd1) -> HHI (fp16) ----
    {
        int row = tid >> 3;
        int c0 = (tid & 7) * 32;
        float dx = sdel[row*3], dy = sdel[row*3+1], dz = sdel[row*3+2];
#pragma unroll
        for (int jp = 0; jp < 16; jp++) {
            int ch = c0 + jp*2;
            float v0 = fmaxf(fmaf(dz, swd1[512+ch],   fmaf(dy, swd1[256+ch],   fmaf(dx, swd1[ch],   sbd1[ch]))), 0.f);
            float v1 = fmaxf(fmaf(dz, swd1[512+ch+1], fmaf(dy, swd1[256+ch+1], fmaf(dx, swd1[ch+1], sbd1[ch+1]))), 0.f);
            *(uint32_t*)(smemc + OFF_HHI + aAddr(row, ch)) = pack2f(v0, v1);
        }
    }
    // (visibility covered by first wait+sync inside run_gemm)

    float acc[8][4];
    int ra = 16*wm + (lane >> 2), rb = ra + 8;

    // ---- GEMM1: D = H1 @ wd2^T ----
    run_gemm(g_wsplit, smemc, sb, OFF_HHI, acc, tid, wm, wn);

    // pre-stage GEMM2 chunk 0 (B buffers idle now, overlaps epi1)
    stage32(g_wsplit +  8*16384, smemc + OFF_B0, tid);
    stage32(g_wsplit + 12*16384, smemc + OFF_B1, tid);

    // ---- epi1: x_k = D + bd2 + feat[idx] -> XHI (fp16) + XF (fp32) ----
    {
        const float* fb = feat + (size_t)b * NN * DD;
        const float* fra = fb + (size_t)sidx[ra] * DD;
        const float* frb = fb + (size_t)sidx[rb] * DD;
#pragma unroll
        for (int t = 0; t < 8; t++) {
            int ne = 64*wn + 8*t + 2*(lane & 3);
            float2 fa = *(const float2*)(fra + ne);
            float2 fv = *(const float2*)(frb + ne);
            float bj0 = __ldg(&bd2[ne]), bj1 = __ldg(&bd2[ne+1]);
            float v0 = acc[t][0] + bj0 + fa.x;
            float v1 = acc[t][1] + bj1 + fa.y;
            float v2 = acc[t][2] + bj0 + fv.x;
            float v3 = acc[t][3] + bj1 + fv.y;
            *(uint32_t*)(smemc + OFF_XHI + aAddr(ra, ne)) = pack2f(v0, v1);
            *(uint32_t*)(smemc + OFF_XHI + aAddr(rb, ne)) = pack2f(v2, v3);
            *(float2*)(xf + ra*260 + ne) = make_float2(v0, v1);
            *(float2*)(xf + rb*260 + ne) = make_float2(v2, v3);
        }
    }

    // ---- GEMM2: D = x_k @ wg1^T ----
    run_gemm(g_wsplit + 8*16384, smemc, sb, OFF_XHI, acc, tid, wm, wn);

    // pre-stage GEMM3 chunk 0
    stage32(g_wsplit + 16*16384, smemc + OFF_B0, tid);
    stage32(g_wsplit + 20*16384, smemc + OFF_B1, tid);

    // ---- epi2: H2 = relu(D + bg1) -> HHI ----
    {
#pragma unroll
        for (int t = 0; t < 8; t++) {
            int ne = 64*wn + 8*t + 2*(lane & 3);
            float bj0 = __ldg(&bg1[ne]), bj1 = __ldg(&bg1[ne+1]);
            float v0 = fmaxf(acc[t][0] + bj0, 0.f);
            float v1 = fmaxf(acc[t][1] + bj1, 0.f);
            float v2 = fmaxf(acc[t][2] + bj0, 0.f);
            float v3 = fmaxf(acc[t][3] + bj1, 0.f);
            *(uint32_t*)(smemc + OFF_HHI + aAddr(ra, ne)) = pack2f(v0, v1);
            *(uint32_t*)(smemc + OFF_HHI + aAddr(rb, ne)) = pack2f(v2, v3);
        }
    }

    // ---- GEMM3: D = H2 @ wg2^T ----
    run_gemm(g_wsplit + 16*16384, smemc, sb, OFF_HHI, acc, tid, wm, wn);

    // ---- softmax over k (warp wm owns point wm's 16 rows) + weighted sum ----
    {
        int n_pt = p0 + wm;
        const float* fpt = feat + ((size_t)b*NN + n_pt) * DD;
        float* orow = out + ((size_t)b*NN + n_pt) * DD;
#pragma unroll
        for (int t = 0; t < 8; t++) {
            int ne = 64*wn + 8*t + 2*(lane & 3);
            float bj0 = __ldg(&bg2[ne]), bj1 = __ldg(&bg2[ne+1]);
            float g0 = acc[t][0] + bj0;
            float g1 = acc[t][1] + bj1;
            float g2 = acc[t][2] + bj0;
            float g3 = acc[t][3] + bj1;
            float2 xa = *(const float2*)(xf + ra*260 + ne);
            float2 xv = *(const float2*)(xf + rb*260 + ne);
            float m0 = fmaxf(g0, g2), m1 = fmaxf(g1, g3);
#pragma unroll
            for (int o = 4; o <= 16; o <<= 1) {
                m0 = fmaxf(m0, __shfl_xor_sync(0xffffffffu, m0, o));
                m1 = fmaxf(m1, __shfl_xor_sync(0xffffffffu, m1, o));
            }
            float e0 = __expf(g0 - m0), e2 = __expf(g2 - m0);
            float e1 = __expf(g1 - m1), e3 = __expf(g3 - m1);
            float se0 = e0 + e2, se1 = e1 + e3;
            float sx0 = e0*xa.x + e2*xv.x, sx1 = e1*xa.y + e3*xv.y;
#pragma unroll
            for (int o = 4; o <= 16; o <<= 1) {
                se0 += __shfl_xor_sync(0xffffffffu, se0, o);
                se1 += __shfl_xor_sync(0xffffffffu, se1, o);
                sx0 += __shfl_xor_sync(0xffffffffu, sx0, o);
                sx1 += __shfl_xor_sync(0xffffffffu, sx1, o);
            }
            if (lane < 4) {
                float2 f = *(const float2*)(fpt + ne);
                float2 o2 = make_float2(f.x + sx0/se0, f.y + sx1/se1);
                *(float2*)(orow + ne) = o2;
            }
        }
    }
}

// ---------------------------------------------------------------------------
extern "C" void kernel_launch(void* const* d_in, const int* in_sizes, int n_in,
                              void* d_out, int out_size) {
    const float* xyz  = (const float*)d_in[0];
    const float* feat = (const float*)d_in[1];
    const float* wd1  = (const float*)d_in[2];
    const float* bd1  = (const float*)d_in[3];
    const float* wd2  = (const float*)d_in[4];
    const float* bd2  = (const float*)d_in[5];
    const float* wg1  = (const float*)d_in[6];
    const float* bg1  = (const float*)d_in[7];
    const float* wg2  = (const float*)d_in[8];
    const float* bg2  = (const float*)d_in[9];
    float* out = (float*)d_out;

    prep_kernel<<<768, 256>>>(wd2, wg1, wg2);
    knn_kernel<<<BB * NN / 8, 256>>>(xyz);

    cudaFuncSetAttribute(mlp_kernel, cudaFuncAttributeMaxDynamicSharedMemorySize, SMEM_TOTAL);
    mlp_kernel<<<BB * NN / PTS, NT, SMEM_TOTAL>>>(xyz, feat, wd1, bd1,
                                                  bd2, bg1, bg2, out);
}